// round 5
// baseline (speedup 1.0000x reference)
#include <cuda_runtime.h>
#include <cuda_bf16.h>

#define W 512
#define H 512
#define IMGS 128                       // 16 * 8
#define STRIP 32                       // output rows per warp
#define STRIPS (H / STRIP)             // 16
#define SEGS 4                         // column segments per row
#define SEGW 128                       // cols per warp segment
#define CPT 4                          // cols per thread
#define WARPS_TOTAL (IMGS * STRIPS * SEGS)   // 8192
#define BLOCK 256
#define WPB (BLOCK / 32)               // 8
#define GRID (WARPS_TOTAL / WPB)       // 1024
#define NELEM 33554432.0f
#define FULLM 0xffffffffu

__device__ float g_partials[GRID];
__device__ unsigned int g_count;       // zero-init; last block resets

struct Carry {
    float xp[CPT];    // x[r-1] at this thread's cols
    float erp[CPT];   // er[r-1]
    float xLp, xRp;   // halo cols of x[r-1] (lane0 / lane31 only)
    float erpR;       // er[r-1][c1+1]     (lane31 only)
};

__device__ __forceinline__ void load4(const float* __restrict__ p, float x[CPT]) {
    float4 a = *reinterpret_cast<const float4*>(p);
    x[0]=a.x; x[1]=a.y; x[2]=a.z; x[3]=a.w;
}

// Consume row r (loaded inline), emit loss for row r-1, advance carry.
__device__ __forceinline__ void step_row(const float* __restrict__ row, int tcol,
                                         int lane, int cL, int cR, bool rightEdge,
                                         Carry& C, float& acc) {
    float xc[CPT];
    load4(row + tcol, xc);
    float xLc = (lane == 0)                ? __ldg(row + cL) : 0.0f;
    float xRc = (!rightEdge && lane == 31) ? __ldg(row + cR) : 0.0f;

    float vm[CPT];
#pragma unroll
    for (int i = 0; i < CPT; i++) vm[i] = fminf(C.xp[i], xc[i]);  // vertical erosion
    float vmL = fminf(C.xLp, xLc);
    float vmR = fminf(C.xRp, xRc);

    // horizontal erosion: er[c] = min(vm[c-1], vm[c])
    float left = __shfl_up_sync(FULLM, vm[CPT-1], 1);
    if (lane == 0) left = vmL;                       // symmetric pad via cL clamp
    float ern[CPT];
    ern[0] = fminf(left, vm[0]);
#pragma unroll
    for (int i = 1; i < CPT; i++) ern[i] = fminf(vm[i-1], vm[i]);
    float ernR = fminf(vm[CPT-1], vmR);

    // vertical dilation for row r-1: h = max(er[r-1], er[r])
    float h[CPT];
#pragma unroll
    for (int i = 0; i < CPT; i++) h[i] = fmaxf(C.erp[i], ern[i]);
    float hR = fmaxf(C.erpR, ernR);

    // horizontal dilation + loss: di[c] = max(h[c], h[c+1])
    float hn = __shfl_down_sync(FULLM, h[0], 1);
    if (lane == 31) hn = rightEdge ? h[CPT-1] : hR;  // er[512]=er[511] at image edge
#pragma unroll
    for (int i = 0; i < CPT-1; i++) {
        float di = fmaxf(h[i], h[i+1]);
        float d = C.xp[i] - di;
        acc = fmaf(d, d, acc);
    }
    {
        float di = fmaxf(h[CPT-1], hn);
        float d = C.xp[CPT-1] - di;
        acc = fmaf(d, d, acc);
    }

#pragma unroll
    for (int i = 0; i < CPT; i++) { C.xp[i] = xc[i]; C.erp[i] = ern[i]; }
    C.xLp = xLc; C.xRp = xRc; C.erpR = ernR;
}

// Emit bottom image row (r = H-1): er[H] := er[H-1], so h == erp.
__device__ __forceinline__ void final_emit(int lane, bool rightEdge, Carry& C, float& acc) {
    float hn = __shfl_down_sync(FULLM, C.erp[0], 1);
    if (lane == 31) hn = rightEdge ? C.erp[CPT-1] : C.erpR;
#pragma unroll
    for (int i = 0; i < CPT-1; i++) {
        float di = fmaxf(C.erp[i], C.erp[i+1]);
        float d = C.xp[i] - di;
        acc = fmaf(d, d, acc);
    }
    float di = fmaxf(C.erp[CPT-1], hn);
    float d = C.xp[CPT-1] - di;
    acc = fmaf(d, d, acc);
}

__global__ void __launch_bounds__(BLOCK, 6)
opening_loss_kernel(const float* __restrict__ labels, float* __restrict__ out) {
    const int lane = threadIdx.x & 31;
    const int warp = blockIdx.x * WPB + (threadIdx.x >> 5);
    const int seg   = warp & (SEGS - 1);
    const int t     = warp >> 2;
    const int strip = t & (STRIPS - 1);
    const int img   = t >> 4;                        // STRIPS==16

    const float* base = labels + (size_t)img * (W * H);
    const int r0 = strip * STRIP;
    const int c0 = seg * SEGW;
    const bool rightEdge = (seg == SEGS - 1);
    const int cL = (c0 == 0) ? 0 : c0 - 1;           // clamp == symmetric pad
    const int cR = c0 + SEGW;                        // only read when !rightEdge
    const int tcol = c0 + lane * CPT;
    const bool lastStrip = (r0 + STRIP == H);

    Carry C;
    float acc = 0.0f;

    // Prologue: erp = er[r0], xp = x[r0]
    {
        const int rm1 = (r0 > 0) ? r0 - 1 : 0;       // x[-1]=x[0] pad
        const float* rowA = base + (size_t)rm1 * W;
        const float* rowB = base + (size_t)r0  * W;
        float xa[CPT], xb[CPT];
        load4(rowA + tcol, xa);
        load4(rowB + tcol, xb);
        float xLa = (lane == 0) ? __ldg(rowA + cL) : 0.0f;
        float xLb = (lane == 0) ? __ldg(rowB + cL) : 0.0f;
        float xRa = (!rightEdge && lane == 31) ? __ldg(rowA + cR) : 0.0f;
        float xRb = (!rightEdge && lane == 31) ? __ldg(rowB + cR) : 0.0f;

        float vm[CPT];
#pragma unroll
        for (int i = 0; i < CPT; i++) vm[i] = fminf(xa[i], xb[i]);
        float vmL = fminf(xLa, xLb);
        float vmR = fminf(xRa, xRb);

        float left = __shfl_up_sync(FULLM, vm[CPT-1], 1);
        if (lane == 0) left = vmL;
        C.erp[0] = fminf(left, vm[0]);
#pragma unroll
        for (int i = 1; i < CPT; i++) C.erp[i] = fminf(vm[i-1], vm[i]);
        C.erpR = fminf(vm[CPT-1], vmR);
#pragma unroll
        for (int i = 0; i < CPT; i++) C.xp[i] = xb[i];
        C.xLp = xLb; C.xRp = xRb;
    }

    if (!lastStrip) {
        const float* row = base + (size_t)(r0 + 1) * W;
#pragma unroll 4
        for (int k = 0; k < STRIP; k++) {
            step_row(row, tcol, lane, cL, cR, rightEdge, C, acc);
            row += W;
        }
    } else {
        const float* row = base + (size_t)(r0 + 1) * W;
        for (int r = r0 + 1; r < H; r++) {
            step_row(row, tcol, lane, cL, cR, rightEdge, C, acc);
            row += W;
        }
        final_emit(lane, rightEdge, C, acc);
    }

    // Deterministic block reduction
#pragma unroll
    for (int off = 16; off; off >>= 1)
        acc += __shfl_xor_sync(FULLM, acc, off);

    __shared__ float s[WPB];
    __shared__ bool is_last;
    if (lane == 0) s[threadIdx.x >> 5] = acc;
    __syncthreads();
    if (threadIdx.x == 0) {
        float tsum = 0.0f;
#pragma unroll
        for (int i = 0; i < WPB; i++) tsum += s[i];
        g_partials[blockIdx.x] = tsum;
        __threadfence();
        unsigned v = atomicAdd(&g_count, 1u);
        is_last = (v == GRID - 1);
    }
    __syncthreads();

    // Last block: deterministic final tree reduction over 1024 partials.
    if (is_last) {
        __shared__ float r[BLOCK];
        r[threadIdx.x] = (g_partials[threadIdx.x]           + g_partials[threadIdx.x + BLOCK])
                       + (g_partials[threadIdx.x + 2*BLOCK] + g_partials[threadIdx.x + 3*BLOCK]);
        __syncthreads();
#pragma unroll
        for (int off = BLOCK / 2; off > 0; off >>= 1) {
            if (threadIdx.x < off) r[threadIdx.x] += r[threadIdx.x + off];
            __syncthreads();
        }
        if (threadIdx.x == 0) {
            out[0] = r[0] * (1.0f / NELEM);
            g_count = 0;    // reset for graph replay
        }
    }
}

extern "C" void kernel_launch(void* const* d_in, const int* in_sizes, int n_in,
                              void* d_out, int out_size) {
    const float* labels = (const float*)d_in[0];
    float* out = (float*)d_out;
    opening_loss_kernel<<<GRID, BLOCK>>>(labels, out);
}

// round 6
// speedup vs baseline: 1.4951x; 1.4951x over previous
#include <cuda_runtime.h>
#include <cuda_bf16.h>

#define W 512
#define H 512
#define IMGS 128                       // 16 * 8
#define STRIP 32                       // output rows per warp
#define STRIPS (H / STRIP)             // 16
#define SEGS 2                         // column segments per row
#define SEGW 256                       // cols per warp segment
#define CPT 8                          // cols per thread
#define WARPS_TOTAL (IMGS * STRIPS * SEGS)   // 4096
#define BLOCK 256
#define WPB (BLOCK / 32)               // 8
#define GRID (WARPS_TOTAL / WPB)       // 512
#define NELEM 33554432.0f
#define FULLM 0xffffffffu

__device__ float g_partials[GRID];
__device__ unsigned int g_count;       // zero-init; last block resets

// Per-thread carry: previous row's x, er, and halo-column values.
struct Carry {
    float xp[CPT];    // x[r-1] at cols [tcol, tcol+7]
    float erp[CPT];   // er[r-1] at same cols
    float xm1p;       // x[r-1][tcol-1]  (clamped)
    float xp1p;       // x[r-1][tcol+8]  (clamped)
    float erpp1;      // er[r-1][tcol+8] (edge-corrected)
};

__device__ __forceinline__ void load8(const float* __restrict__ p, float x[CPT]) {
    float4 a = *reinterpret_cast<const float4*>(p);
    float4 b = *reinterpret_cast<const float4*>(p + 4);
    x[0]=a.x; x[1]=a.y; x[2]=a.z; x[3]=a.w;
    x[4]=b.x; x[5]=b.y; x[6]=b.z; x[7]=b.w;
}

// Pure-thread step: consume row r, emit loss for row r-1. No cross-lane ops.
__device__ __forceinline__ void step_row(const float* __restrict__ row, int tcol,
                                         int im1, int ip1, bool atRight,
                                         Carry& C, float& acc) {
    float xc[CPT];
    load8(row + tcol, xc);
    float xm1c = __ldg(row + im1);     // left halo  (L1 hit: same lines)
    float xp1c = __ldg(row + ip1);     // right halo (L1 hit)

    // vertical erosion
    float vm[CPT];
#pragma unroll
    for (int i = 0; i < CPT; i++) vm[i] = fminf(C.xp[i], xc[i]);
    float vmm1 = fminf(C.xm1p, xm1c);
    float vmp1 = fminf(C.xp1p, xp1c);

    // horizontal erosion: er[c] = min(vm[c-1], vm[c]); left clamp == symmetric pad
    float ern[CPT];
    ern[0] = fminf(vmm1, vm[0]);
#pragma unroll
    for (int i = 1; i < CPT; i++) ern[i] = fminf(vm[i-1], vm[i]);
    float ernp1 = atRight ? ern[CPT-1] : fminf(vm[CPT-1], vmp1);  // er[512]:=er[511]

    // vertical dilation for row r-1
    float h[CPT];
#pragma unroll
    for (int i = 0; i < CPT; i++) h[i] = fmaxf(C.erp[i], ern[i]);
    float hp1 = fmaxf(C.erpp1, ernp1);

    // horizontal dilation + loss
#pragma unroll
    for (int i = 0; i < CPT-1; i++) {
        float di = fmaxf(h[i], h[i+1]);
        float d = C.xp[i] - di;
        acc = fmaf(d, d, acc);
    }
    {
        float di = fmaxf(h[CPT-1], hp1);
        float d = C.xp[CPT-1] - di;
        acc = fmaf(d, d, acc);
    }

    // advance carry
#pragma unroll
    for (int i = 0; i < CPT; i++) { C.xp[i] = xc[i]; C.erp[i] = ern[i]; }
    C.xm1p = xm1c; C.xp1p = xp1c; C.erpp1 = ernp1;
}

// Emit bottom image row (r = H-1): er[H] := er[H-1] -> h == erp.
__device__ __forceinline__ void final_emit(Carry& C, float& acc) {
#pragma unroll
    for (int i = 0; i < CPT-1; i++) {
        float di = fmaxf(C.erp[i], C.erp[i+1]);
        float d = C.xp[i] - di;
        acc = fmaf(d, d, acc);
    }
    float di = fmaxf(C.erp[CPT-1], C.erpp1);   // erpp1 already edge-corrected
    float d = C.xp[CPT-1] - di;
    acc = fmaf(d, d, acc);
}

__global__ void __launch_bounds__(BLOCK, 4)
opening_loss_kernel(const float* __restrict__ labels, float* __restrict__ out) {
    const int lane = threadIdx.x & 31;
    const int warp = blockIdx.x * WPB + (threadIdx.x >> 5);
    const int seg   = warp & (SEGS - 1);
    const int t     = warp >> 1;
    const int strip = t & (STRIPS - 1);
    const int img   = t >> 4;                        // STRIPS==16

    const float* base = labels + (size_t)img * (W * H);
    const int r0 = strip * STRIP;
    const int tcol = seg * SEGW + lane * CPT;
    const int im1 = (tcol > 0) ? tcol - 1 : 0;       // clamp == symmetric pad
    const bool atRight = (tcol + CPT == W);
    const int ip1 = atRight ? (W - 1) : tcol + CPT;  // value unused when atRight
    const bool lastStrip = (r0 + STRIP == H);

    Carry C;
    float acc = 0.0f;

    // Prologue: erp = er[r0], xp = x[r0]
    {
        const int rm1 = (r0 > 0) ? r0 - 1 : 0;       // x[-1]=x[0] pad
        const float* rowA = base + (size_t)rm1 * W;
        const float* rowB = base + (size_t)r0  * W;
        float xa[CPT], xb[CPT];
        load8(rowA + tcol, xa);
        load8(rowB + tcol, xb);
        float xm1a = __ldg(rowA + im1), xm1b = __ldg(rowB + im1);
        float xp1a = __ldg(rowA + ip1), xp1b = __ldg(rowB + ip1);

        float vm[CPT];
#pragma unroll
        for (int i = 0; i < CPT; i++) vm[i] = fminf(xa[i], xb[i]);
        float vmm1 = fminf(xm1a, xm1b);
        float vmp1 = fminf(xp1a, xp1b);

        C.erp[0] = fminf(vmm1, vm[0]);
#pragma unroll
        for (int i = 1; i < CPT; i++) C.erp[i] = fminf(vm[i-1], vm[i]);
        C.erpp1 = atRight ? C.erp[CPT-1] : fminf(vm[CPT-1], vmp1);
#pragma unroll
        for (int i = 0; i < CPT; i++) C.xp[i] = xb[i];
        C.xm1p = xm1b; C.xp1p = xp1b;
    }

    if (!lastStrip) {
        const float* row = base + (size_t)(r0 + 1) * W;
#pragma unroll 4
        for (int k = 0; k < STRIP; k++) {
            step_row(row, tcol, im1, ip1, atRight, C, acc);
            row += W;
        }
    } else {
        const float* row = base + (size_t)(r0 + 1) * W;
        for (int r = r0 + 1; r < H; r++) {
            step_row(row, tcol, im1, ip1, atRight, C, acc);
            row += W;
        }
        final_emit(C, acc);
    }

    // Deterministic block reduction
#pragma unroll
    for (int off = 16; off; off >>= 1)
        acc += __shfl_xor_sync(FULLM, acc, off);

    __shared__ float s[WPB];
    __shared__ bool is_last;
    if (lane == 0) s[threadIdx.x >> 5] = acc;
    __syncthreads();
    if (threadIdx.x == 0) {
        float tsum = 0.0f;
#pragma unroll
        for (int i = 0; i < WPB; i++) tsum += s[i];
        g_partials[blockIdx.x] = tsum;
        __threadfence();
        unsigned v = atomicAdd(&g_count, 1u);
        is_last = (v == GRID - 1);
    }
    __syncthreads();

    // Last block: deterministic final tree reduction over 512 partials.
    if (is_last) {
        __shared__ float r[BLOCK];
        r[threadIdx.x] = g_partials[threadIdx.x] + g_partials[threadIdx.x + BLOCK];
        __syncthreads();
#pragma unroll
        for (int off = BLOCK / 2; off > 0; off >>= 1) {
            if (threadIdx.x < off) r[threadIdx.x] += r[threadIdx.x + off];
            __syncthreads();
        }
        if (threadIdx.x == 0) {
            out[0] = r[0] * (1.0f / NELEM);
            g_count = 0;    // reset for graph replay
        }
    }
}

extern "C" void kernel_launch(void* const* d_in, const int* in_sizes, int n_in,
                              void* d_out, int out_size) {
    const float* labels = (const float*)d_in[0];
    float* out = (float*)d_out;
    opening_loss_kernel<<<GRID, BLOCK>>>(labels, out);
}

// round 7
// speedup vs baseline: 1.4981x; 1.0019x over previous
#include <cuda_runtime.h>
#include <cuda_bf16.h>

#define W 512
#define H 512
#define IMGS 128                       // 16 * 8
#define STRIP 32                       // output rows per warp-task
#define STRIPS (H / STRIP)             // 16
#define SEGS 2                         // column segments per row
#define SEGW 256                       // cols per warp segment
#define CPT 8                          // cols per thread
#define TASKS (IMGS * STRIPS * SEGS)   // 4096 warp-tasks
#define BLOCK 256
#define WPB (BLOCK / 32)               // 8
#define GRID 592                       // 4 * 148 SMs -> perfectly uniform wave
#define NELEM 33554432.0f
#define FULLM 0xffffffffu

__device__ float g_partials[GRID];
__device__ unsigned int g_count;       // zero-init; last block resets

struct Carry {
    float xp[CPT];    // x[r-1] at this thread's cols
    float erp[CPT];   // er[r-1]
    float xLp, xRp;   // halo cols of x[r-1] (lane0 / lane31 only)
    float erpR;       // er[r-1][c1+1]     (lane31 only)
};

__device__ __forceinline__ void load8(const float* __restrict__ p, float x[CPT]) {
    float4 a = *reinterpret_cast<const float4*>(p);
    float4 b = *reinterpret_cast<const float4*>(p + 4);
    x[0]=a.x; x[1]=a.y; x[2]=a.z; x[3]=a.w;
    x[4]=b.x; x[5]=b.y; x[6]=b.z; x[7]=b.w;
}

// Consume row r, emit loss for row r-1.
__device__ __forceinline__ void step_row(const float* __restrict__ tp,
                                         const float* __restrict__ row,
                                         int lane, int cL, int cR, bool rightEdge,
                                         Carry& C, float& acc) {
    float xc[CPT];
    load8(tp, xc);
    float xLc = (lane == 0)                ? __ldg(row + cL) : 0.0f;
    float xRc = (!rightEdge && lane == 31) ? __ldg(row + cR) : 0.0f;

    float vm[CPT];
#pragma unroll
    for (int i = 0; i < CPT; i++) vm[i] = fminf(C.xp[i], xc[i]);  // vertical erosion
    float vmL = fminf(C.xLp, xLc);
    float vmR = fminf(C.xRp, xRc);

    // horizontal erosion: er[c] = min(vm[c-1], vm[c])
    float left = __shfl_up_sync(FULLM, vm[CPT-1], 1);
    if (lane == 0) left = vmL;                       // symmetric pad via cL clamp
    float ern[CPT];
    ern[0] = fminf(left, vm[0]);
#pragma unroll
    for (int i = 1; i < CPT; i++) ern[i] = fminf(vm[i-1], vm[i]);
    float ernR = fminf(vm[CPT-1], vmR);

    // vertical dilation for row r-1: h = max(er[r-1], er[r])
    float h[CPT];
#pragma unroll
    for (int i = 0; i < CPT; i++) h[i] = fmaxf(C.erp[i], ern[i]);
    float hR = fmaxf(C.erpR, ernR);

    // horizontal dilation + loss: di[c] = max(h[c], h[c+1])
    float hn = __shfl_down_sync(FULLM, h[0], 1);
    if (lane == 31) hn = rightEdge ? h[CPT-1] : hR;  // er[512]=er[511] at image edge
#pragma unroll
    for (int i = 0; i < CPT-1; i++) {
        float di = fmaxf(h[i], h[i+1]);
        float d = C.xp[i] - di;
        acc = fmaf(d, d, acc);
    }
    {
        float di = fmaxf(h[CPT-1], hn);
        float d = C.xp[CPT-1] - di;
        acc = fmaf(d, d, acc);
    }

#pragma unroll
    for (int i = 0; i < CPT; i++) { C.xp[i] = xc[i]; C.erp[i] = ern[i]; }
    C.xLp = xLc; C.xRp = xRc; C.erpR = ernR;
}

// Emit bottom image row (r = H-1): er[H] := er[H-1], so h == erp.
__device__ __forceinline__ void final_emit(int lane, bool rightEdge, Carry& C, float& acc) {
    float hn = __shfl_down_sync(FULLM, C.erp[0], 1);
    if (lane == 31) hn = rightEdge ? C.erp[CPT-1] : C.erpR;
#pragma unroll
    for (int i = 0; i < CPT-1; i++) {
        float di = fmaxf(C.erp[i], C.erp[i+1]);
        float d = C.xp[i] - di;
        acc = fmaf(d, d, acc);
    }
    float di = fmaxf(C.erp[CPT-1], hn);
    float d = C.xp[CPT-1] - di;
    acc = fmaf(d, d, acc);
}

__global__ void __launch_bounds__(BLOCK, 4)
opening_loss_kernel(const float* __restrict__ labels, float* __restrict__ out) {
    const int lane = threadIdx.x & 31;
    const int warp = blockIdx.x * WPB + (threadIdx.x >> 5);
    float acc = 0.0f;

    if (warp < TASKS) {
        const int seg   = warp & (SEGS - 1);
        const int t     = warp >> 1;
        const int strip = t & (STRIPS - 1);
        const int img   = t >> 4;                        // STRIPS==16

        const float* base = labels + (size_t)img * (W * H);
        const int r0 = strip * STRIP;
        const int c0 = seg * SEGW;
        const bool rightEdge = (seg == SEGS - 1);
        const int cL = (c0 == 0) ? 0 : c0 - 1;           // clamp == symmetric pad
        const int cR = rightEdge ? (W - 1) : c0 + SEGW;  // never loaded when rightEdge
        const int tcol = c0 + lane * CPT;
        const bool lastStrip = (r0 + STRIP == H);

        Carry C;

        // Prologue: erp = er[r0], xp = x[r0]
        {
            const int rm1 = (r0 > 0) ? r0 - 1 : 0;       // x[-1]=x[0] pad
            const float* rowA = base + (size_t)rm1 * W;
            const float* rowB = base + (size_t)r0  * W;
            float xa[CPT], xb[CPT];
            load8(rowA + tcol, xa);
            load8(rowB + tcol, xb);
            float xLa = (lane == 0) ? __ldg(rowA + cL) : 0.0f;
            float xLb = (lane == 0) ? __ldg(rowB + cL) : 0.0f;
            float xRa = (!rightEdge && lane == 31) ? __ldg(rowA + cR) : 0.0f;
            float xRb = (!rightEdge && lane == 31) ? __ldg(rowB + cR) : 0.0f;

            float vm[CPT];
#pragma unroll
            for (int i = 0; i < CPT; i++) vm[i] = fminf(xa[i], xb[i]);
            float vmL = fminf(xLa, xLb);
            float vmR = fminf(xRa, xRb);

            float left = __shfl_up_sync(FULLM, vm[CPT-1], 1);
            if (lane == 0) left = vmL;
            C.erp[0] = fminf(left, vm[0]);
#pragma unroll
            for (int i = 1; i < CPT; i++) C.erp[i] = fminf(vm[i-1], vm[i]);
            C.erpR = fminf(vm[CPT-1], vmR);
#pragma unroll
            for (int i = 0; i < CPT; i++) C.xp[i] = xb[i];
            C.xLp = xLb; C.xRp = xRb;
        }

        if (!lastStrip) {
            const float* row = base + (size_t)(r0 + 1) * W;
#pragma unroll 4
            for (int k = 0; k < STRIP; k++) {
                step_row(row + tcol, row, lane, cL, cR, rightEdge, C, acc);
                row += W;
            }
        } else {
            const float* row = base + (size_t)(r0 + 1) * W;
            for (int r = r0 + 1; r < H; r++) {
                step_row(row + tcol, row, lane, cL, cR, rightEdge, C, acc);
                row += W;
            }
            final_emit(lane, rightEdge, C, acc);
        }
    }

    // Deterministic block reduction (all warps participate; idle warps add 0)
#pragma unroll
    for (int off = 16; off; off >>= 1)
        acc += __shfl_xor_sync(FULLM, acc, off);

    __shared__ float s[WPB];
    __shared__ bool is_last;
    if (lane == 0) s[threadIdx.x >> 5] = acc;
    __syncthreads();
    if (threadIdx.x == 0) {
        float tsum = 0.0f;
#pragma unroll
        for (int i = 0; i < WPB; i++) tsum += s[i];
        g_partials[blockIdx.x] = tsum;
        __threadfence();
        unsigned v = atomicAdd(&g_count, 1u);
        is_last = (v == GRID - 1);
    }
    __syncthreads();

    // Last block: deterministic final tree reduction over 592 partials.
    if (is_last) {
        __shared__ float r[BLOCK];
        float v = g_partials[threadIdx.x] + g_partials[threadIdx.x + BLOCK];
        if (threadIdx.x < GRID - 2 * BLOCK)              // 592 - 512 = 80
            v += g_partials[threadIdx.x + 2 * BLOCK];
        r[threadIdx.x] = v;
        __syncthreads();
#pragma unroll
        for (int off = BLOCK / 2; off > 0; off >>= 1) {
            if (threadIdx.x < off) r[threadIdx.x] += r[threadIdx.x + off];
            __syncthreads();
        }
        if (threadIdx.x == 0) {
            out[0] = r[0] * (1.0f / NELEM);
            g_count = 0;    // reset for graph replay
        }
    }
}

extern "C" void kernel_launch(void* const* d_in, const int* in_sizes, int n_in,
                              void* d_out, int out_size) {
    const float* labels = (const float*)d_in[0];
    float* out = (float*)d_out;
    opening_loss_kernel<<<GRID, BLOCK>>>(labels, out);
}